// round 1
// baseline (speedup 1.0000x reference)
#include <cuda_runtime.h>
#include <math.h>

// Problem constants
#define NROWS  2048      // B*N
#define DMODEL 1024
#define NHEAD  16
#define DHEAD  64
#define DFF    4096
#define NVOCAB 32000
#define NLAYER 6

// ---------------- device scratch (no allocation allowed) ----------------
__device__ float g_h  [NROWS * DMODEL];
__device__ float g_xn [NROWS * DMODEL];
__device__ float g_qkv[NROWS * 3 * DMODEL];
__device__ float g_o  [NROWS * DMODEL];
__device__ float g_ff [NROWS * DFF];

// ---------------- helpers ----------------
__device__ __forceinline__ float geluf(float x) {
    return 0.5f * x * (1.0f + erff(x * 0.70710678118654752f));
}

__device__ __forceinline__ float block_sum256(float v, float* sred) {
#pragma unroll
    for (int o = 16; o > 0; o >>= 1) v += __shfl_xor_sync(0xffffffffu, v, o);
    int w = threadIdx.x >> 5;
    if ((threadIdx.x & 31) == 0) sred[w] = v;
    __syncthreads();
    float t = sred[threadIdx.x & 7];
#pragma unroll
    for (int o = 4; o > 0; o >>= 1) t += __shfl_xor_sync(0xffffffffu, t, o);
    __syncthreads();   // sred reusable after return
    return t;
}

// ---------------- embedding: h = token_emb[x] + pos_emb ----------------
__global__ __launch_bounds__(256) void embed_kernel(
    const int* __restrict__ x, const float* __restrict__ tok,
    const float* __restrict__ pos, float* __restrict__ h)
{
    int i = blockIdx.x * 256 + threadIdx.x;  // float4 index over 2048*256
    int row = i >> 8;
    int d4  = i & 255;
    int n = row & 1023;
    int t = x[row];
    float4 a = ((const float4*)(tok + (size_t)t * DMODEL))[d4];
    float4 p = ((const float4*)(pos + (size_t)n * DMODEL))[d4];
    a.x += p.x; a.y += p.y; a.z += p.z; a.w += p.w;
    ((float4*)(h + (size_t)row * DMODEL))[d4] = a;
}

// ---------------- layernorm (two-pass, in registers) ----------------
__global__ __launch_bounds__(256) void ln_kernel(
    const float* __restrict__ in, float* __restrict__ out,
    const float* __restrict__ gw, const float* __restrict__ bw)
{
    __shared__ float sred[8];
    const int row = blockIdx.x;
    const int tid = threadIdx.x;
    float4 v = ((const float4*)(in + (size_t)row * DMODEL))[tid];
    float s = v.x + v.y + v.z + v.w;
    float tot = block_sum256(s, sred);
    float mean = tot * (1.0f / (float)DMODEL);
    float d0 = v.x - mean, d1 = v.y - mean, d2 = v.z - mean, d3 = v.w - mean;
    float s2 = d0 * d0 + d1 * d1 + d2 * d2 + d3 * d3;
    float tot2 = block_sum256(s2, sred);
    float var = tot2 * (1.0f / (float)DMODEL);
    float rstd = rsqrtf(var + 1e-5f);
    float4 gg = ((const float4*)gw)[tid];
    float4 bb = ((const float4*)bw)[tid];
    float4 o;
    o.x = d0 * rstd * gg.x + bb.x;
    o.y = d1 * rstd * gg.y + bb.y;
    o.z = d2 * rstd * gg.z + bb.z;
    o.w = d3 * rstd * gg.w + bb.w;
    ((float4*)(out + (size_t)row * DMODEL))[tid] = o;
}

// ---------------- l2-normalize q and k heads in-place ----------------
__global__ __launch_bounds__(256) void l2n_kernel(float* __restrict__ qkv)
{
    int wid  = (blockIdx.x * 256 + threadIdx.x) >> 5;   // global warp id, 65536 total
    int lane = threadIdx.x & 31;
    int row   = wid >> 5;          // 0..2047
    int rem   = wid & 31;
    int which = rem >> 4;          // 0 = q, 1 = k
    int h     = rem & 15;
    float* p = qkv + (size_t)row * (3 * DMODEL) + which * DMODEL + h * DHEAD;
    float2 v = *(float2*)(p + lane * 2);
    float ss = v.x * v.x + v.y * v.y;
#pragma unroll
    for (int o = 16; o > 0; o >>= 1) ss += __shfl_xor_sync(0xffffffffu, ss, o);
    float inv = rsqrtf(ss);
    v.x *= inv; v.y *= inv;
    *(float2*)(p + lane * 2) = v;
}

// ---------------- flash attention (cosine-sim, causal) ----------------
// Block: one (b,h) and a 64-query tile. Threads: 256 (r = tid>>2, g = tid&3).
// Key tiles of 32. Q/K already l2-normalized; scale 8.0.
__global__ __launch_bounds__(256) void flash_kernel(
    const float* __restrict__ qkv, float* __restrict__ out)
{
    __shared__ float Qs[64 * 68];   // [r][d], padded
    __shared__ float Kt[64 * 32];   // [d][j]
    __shared__ float Vs[32 * 64];   // [j][d]
    __shared__ float Ps[64 * 36];   // [r][j], padded
    __shared__ float red[64 * 4];

    const int bh = blockIdx.x;   // 0..31
    const int qb = blockIdx.y;   // 0..15
    const int b = bh >> 4, h = bh & 15;
    const int tid = threadIdx.x;
    const int r = tid >> 2;
    const int g = tid & 3;

    const float* qbase = qkv + (size_t)b * 1024 * (3 * DMODEL) + h * DHEAD;
    const float* kbase = qbase + DMODEL;
    const float* vbase = qbase + 2 * DMODEL;

    // load Q tile: 64 rows x 64 dims
    for (int t = tid; t < 64 * 16; t += 256) {
        int row = t >> 4;
        int d4  = (t & 15) << 2;
        float4 v = *(const float4*)(qbase + (size_t)(qb * 64 + row) * (3 * DMODEL) + d4);
        *(float4*)(&Qs[row * 68 + d4]) = v;
    }

    float m_run = -1e30f, l_run = 0.f;
    float acc[16];
#pragma unroll
    for (int i = 0; i < 16; i++) acc[i] = 0.f;

    const int iglob = qb * 64 + r;
    const int nkb = 2 * (qb + 1);
    const int c0 = g * 8;
    const int dd0 = g * 16;

    for (int kb = 0; kb < nkb; kb++) {
        __syncthreads();
        // K tile transposed: [d][j]
        for (int t = tid; t < 512; t += 256) {
            int row = t & 31;
            int d4  = (t >> 5) << 2;
            float4 v = *(const float4*)(kbase + (size_t)(kb * 32 + row) * (3 * DMODEL) + d4);
            Kt[(d4 + 0) * 32 + row] = v.x;
            Kt[(d4 + 1) * 32 + row] = v.y;
            Kt[(d4 + 2) * 32 + row] = v.z;
            Kt[(d4 + 3) * 32 + row] = v.w;
        }
        // V tile: [j][d]
        for (int t = tid; t < 512; t += 256) {
            int row = t >> 4;
            int d4  = (t & 15) << 2;
            *(float4*)(&Vs[row * 64 + d4]) =
                *(const float4*)(vbase + (size_t)(kb * 32 + row) * (3 * DMODEL) + d4);
        }
        __syncthreads();

        // S = q . k for 8 keys
        float s[8];
#pragma unroll
        for (int j = 0; j < 8; j++) s[j] = 0.f;
#pragma unroll 4
        for (int d = 0; d < 64; d++) {
            float qd = Qs[r * 68 + d];
            float4 k0 = *(const float4*)(&Kt[d * 32 + c0]);
            float4 k1 = *(const float4*)(&Kt[d * 32 + c0 + 4]);
            s[0] = fmaf(qd, k0.x, s[0]); s[1] = fmaf(qd, k0.y, s[1]);
            s[2] = fmaf(qd, k0.z, s[2]); s[3] = fmaf(qd, k0.w, s[3]);
            s[4] = fmaf(qd, k1.x, s[4]); s[5] = fmaf(qd, k1.y, s[5]);
            s[6] = fmaf(qd, k1.z, s[6]); s[7] = fmaf(qd, k1.w, s[7]);
        }
        float lmax = -1e30f;
#pragma unroll
        for (int j = 0; j < 8; j++) {
            int jg = kb * 32 + c0 + j;
            s[j] = (jg <= iglob) ? s[j] * 8.0f : -1e30f;
            lmax = fmaxf(lmax, s[j]);
        }
        red[r * 4 + g] = lmax;
        __syncthreads();
        float tmax = fmaxf(fmaxf(red[r * 4 + 0], red[r * 4 + 1]),
                           fmaxf(red[r * 4 + 2], red[r * 4 + 3]));
        float m_new = fmaxf(m_run, tmax);
        float alpha = __expf(m_run - m_new);
        float lsum = 0.f;
#pragma unroll
        for (int j = 0; j < 8; j++) { float p = __expf(s[j] - m_new); s[j] = p; lsum += p; }
        __syncthreads();   // everyone done reading red
        red[r * 4 + g] = lsum;
        *(float4*)(&Ps[r * 36 + c0])     = make_float4(s[0], s[1], s[2], s[3]);
        *(float4*)(&Ps[r * 36 + c0 + 4]) = make_float4(s[4], s[5], s[6], s[7]);
        __syncthreads();
        float tsum = red[r * 4 + 0] + red[r * 4 + 1] + red[r * 4 + 2] + red[r * 4 + 3];
        l_run = l_run * alpha + tsum;
        m_run = m_new;
#pragma unroll
        for (int i = 0; i < 16; i++) acc[i] *= alpha;
        // O += P @ V  (this thread: row r, dims dd0..dd0+15)
        for (int j = 0; j < 32; j++) {
            float p = Ps[r * 36 + j];
            const float4* v4 = (const float4*)(&Vs[j * 64 + dd0]);
            float4 v0 = v4[0], v1 = v4[1], v2 = v4[2], v3 = v4[3];
            acc[0]  = fmaf(p, v0.x, acc[0]);  acc[1]  = fmaf(p, v0.y, acc[1]);
            acc[2]  = fmaf(p, v0.z, acc[2]);  acc[3]  = fmaf(p, v0.w, acc[3]);
            acc[4]  = fmaf(p, v1.x, acc[4]);  acc[5]  = fmaf(p, v1.y, acc[5]);
            acc[6]  = fmaf(p, v1.z, acc[6]);  acc[7]  = fmaf(p, v1.w, acc[7]);
            acc[8]  = fmaf(p, v2.x, acc[8]);  acc[9]  = fmaf(p, v2.y, acc[9]);
            acc[10] = fmaf(p, v2.z, acc[10]); acc[11] = fmaf(p, v2.w, acc[11]);
            acc[12] = fmaf(p, v3.x, acc[12]); acc[13] = fmaf(p, v3.y, acc[13]);
            acc[14] = fmaf(p, v3.z, acc[14]); acc[15] = fmaf(p, v3.w, acc[15]);
        }
    }
    float inv = 1.f / l_run;
    float* ob = out + (size_t)(b * 1024 + iglob) * DMODEL + h * DHEAD + dd0;
#pragma unroll
    for (int q = 0; q < 4; q++) {
        float4 v = make_float4(acc[q * 4] * inv, acc[q * 4 + 1] * inv,
                               acc[q * 4 + 2] * inv, acc[q * 4 + 3] * inv);
        *(float4*)(ob + q * 4) = v;
    }
}

// ---------------- SGEMM 128x128x8, 8x8 register tiles ----------------
// EPI: 0=none, 1=+bias, 2=+bias+gelu, 3=+residual, 4=+bias+residual
template<int EPI>
__global__ __launch_bounds__(256) void sgemm_kernel(
    const float* __restrict__ A, const float* __restrict__ B, float* __restrict__ C,
    int M, int N, int K,
    const float* __restrict__ bias, const float* __restrict__ res)
{
    __shared__ float As[8][128];
    __shared__ float Bs[8][128];
    const int bn = blockIdx.x, bm = blockIdx.y;
    const int tid = threadIdx.x;
    const int tx = tid & 15, ty = tid >> 4;

    const float* Ab = A + (size_t)bm * 128 * K;
    const float* Bb = B + (size_t)bn * 128;

    const int arow = tid >> 1;
    const int acol = (tid & 1) << 2;
    const int brow = tid >> 5;
    const int bcol = (tid & 31) << 2;

    float acc[8][8];
#pragma unroll
    for (int i = 0; i < 8; i++)
#pragma unroll
        for (int j = 0; j < 8; j++) acc[i][j] = 0.f;

    for (int kt = 0; kt < K; kt += 8) {
        float4 a4 = *(const float4*)(Ab + (size_t)arow * K + kt + acol);
        float4 b4 = *(const float4*)(Bb + (size_t)(kt + brow) * N + bcol);
        As[acol + 0][arow] = a4.x;
        As[acol + 1][arow] = a4.y;
        As[acol + 2][arow] = a4.z;
        As[acol + 3][arow] = a4.w;
        *(float4*)(&Bs[brow][bcol]) = b4;
        __syncthreads();
#pragma unroll
        for (int k = 0; k < 8; k++) {
            float4 a0 = *(const float4*)(&As[k][ty * 8]);
            float4 a1 = *(const float4*)(&As[k][ty * 8 + 4]);
            float4 b0 = *(const float4*)(&Bs[k][tx * 8]);
            float4 b1 = *(const float4*)(&Bs[k][tx * 8 + 4]);
            float ar[8] = {a0.x, a0.y, a0.z, a0.w, a1.x, a1.y, a1.z, a1.w};
            float br[8] = {b0.x, b0.y, b0.z, b0.w, b1.x, b1.y, b1.z, b1.w};
#pragma unroll
            for (int i = 0; i < 8; i++)
#pragma unroll
                for (int j = 0; j < 8; j++)
                    acc[i][j] = fmaf(ar[i], br[j], acc[i][j]);
        }
        __syncthreads();
    }

    float bv[8];
    if (EPI == 1 || EPI == 2 || EPI == 4) {
        float4 bb0 = *(const float4*)(bias + bn * 128 + tx * 8);
        float4 bb1 = *(const float4*)(bias + bn * 128 + tx * 8 + 4);
        bv[0] = bb0.x; bv[1] = bb0.y; bv[2] = bb0.z; bv[3] = bb0.w;
        bv[4] = bb1.x; bv[5] = bb1.y; bv[6] = bb1.z; bv[7] = bb1.w;
    }
#pragma unroll
    for (int i = 0; i < 8; i++) {
        size_t off = (size_t)(bm * 128 + ty * 8 + i) * N + bn * 128 + tx * 8;
#pragma unroll
        for (int j4 = 0; j4 < 2; j4++) {
            float4 v = make_float4(acc[i][j4 * 4], acc[i][j4 * 4 + 1],
                                   acc[i][j4 * 4 + 2], acc[i][j4 * 4 + 3]);
            if (EPI == 1 || EPI == 2 || EPI == 4) {
                v.x += bv[j4 * 4]; v.y += bv[j4 * 4 + 1];
                v.z += bv[j4 * 4 + 2]; v.w += bv[j4 * 4 + 3];
            }
            if (EPI == 2) {
                v.x = geluf(v.x); v.y = geluf(v.y);
                v.z = geluf(v.z); v.w = geluf(v.w);
            }
            if (EPI == 3 || EPI == 4) {
                float4 rv = *(const float4*)(res + off + j4 * 4);
                v.x += rv.x; v.y += rv.y; v.z += rv.z; v.w += rv.w;
            }
            *(float4*)(C + off + j4 * 4) = v;
        }
    }
}

// ---------------- launch ----------------
extern "C" void kernel_launch(void* const* d_in, const int* in_sizes, int n_in,
                              void* d_out, int out_size)
{
    const int*   x       = (const int*)  d_in[0];
    const float* tok     = (const float*)d_in[1];
    const float* pos     = (const float*)d_in[2];
    const float* ln1_g   = (const float*)d_in[3];
    const float* ln1_b   = (const float*)d_in[4];
    const float* w_qkv   = (const float*)d_in[5];
    const float* w_out   = (const float*)d_in[6];
    const float* ln2_g   = (const float*)d_in[7];
    const float* ln2_b   = (const float*)d_in[8];
    const float* w1      = (const float*)d_in[9];
    const float* b1      = (const float*)d_in[10];
    const float* w2      = (const float*)d_in[11];
    const float* b2      = (const float*)d_in[12];
    const float* lnf_g   = (const float*)d_in[13];
    const float* lnf_b   = (const float*)d_in[14];
    const float* w_logit = (const float*)d_in[15];
    const float* b_logit = (const float*)d_in[16];
    float* out = (float*)d_out;

    void *ph, *pxn, *pqkv, *po, *pff;
    cudaGetSymbolAddress(&ph,  g_h);
    cudaGetSymbolAddress(&pxn, g_xn);
    cudaGetSymbolAddress(&pqkv,g_qkv);
    cudaGetSymbolAddress(&po,  g_o);
    cudaGetSymbolAddress(&pff, g_ff);
    float* h   = (float*)ph;
    float* xn  = (float*)pxn;
    float* qkv = (float*)pqkv;
    float* o   = (float*)po;
    float* ff  = (float*)pff;

    embed_kernel<<<2048, 256>>>(x, tok, pos, h);

    for (int l = 0; l < NLAYER; l++) {
        ln_kernel<<<NROWS, 256>>>(h, xn, ln1_g + l * DMODEL, ln1_b + l * DMODEL);
        sgemm_kernel<0><<<dim3(3072 / 128, NROWS / 128), 256>>>(
            xn, w_qkv + (size_t)l * DMODEL * 3072, qkv, NROWS, 3072, DMODEL,
            nullptr, nullptr);
        l2n_kernel<<<8192, 256>>>(qkv);
        flash_kernel<<<dim3(32, 16), 256>>>(qkv, o);
        sgemm_kernel<3><<<dim3(DMODEL / 128, NROWS / 128), 256>>>(
            o, w_out + (size_t)l * DMODEL * DMODEL, h, NROWS, DMODEL, DMODEL,
            nullptr, h);
        ln_kernel<<<NROWS, 256>>>(h, xn, ln2_g + l * DMODEL, ln2_b + l * DMODEL);
        sgemm_kernel<2><<<dim3(DFF / 128, NROWS / 128), 256>>>(
            xn, w1 + (size_t)l * DMODEL * DFF, ff, NROWS, DFF, DMODEL,
            b1 + l * DFF, nullptr);
        sgemm_kernel<4><<<dim3(DMODEL / 128, NROWS / 128), 256>>>(
            ff, w2 + (size_t)l * DFF * DMODEL, h, NROWS, DMODEL, DFF,
            b2 + l * DMODEL, h);
    }

    ln_kernel<<<NROWS, 256>>>(h, xn, lnf_g, lnf_b);
    sgemm_kernel<1><<<dim3(NVOCAB / 128, NROWS / 128), 256>>>(
        xn, w_logit, out, NROWS, NVOCAB, DMODEL, b_logit, nullptr);
}

// round 3
// speedup vs baseline: 1.9330x; 1.9330x over previous
#include <cuda_runtime.h>
#include <cuda_bf16.h>
#include <math.h>
#include <stdint.h>

// Problem constants
#define NROWS  2048      // B*N
#define DMODEL 1024
#define NHEAD  16
#define DHEAD  64
#define DFF    4096
#define NVOCAB 32000
#define NLAYER 6

// ---------------- device scratch (no allocation allowed) ----------------
__device__ float g_h  [NROWS * DMODEL];
__device__ float g_xn [NROWS * DMODEL];
__device__ float g_qkv[NROWS * 3 * DMODEL];
__device__ float g_o  [NROWS * DMODEL];
__device__ float g_ff [NROWS * DFF];

// ---------------- helpers ----------------
__device__ __forceinline__ float geluf(float x) {
    return 0.5f * x * (1.0f + erff(x * 0.70710678118654752f));
}

__device__ __forceinline__ float block_sum256(float v, float* sred) {
#pragma unroll
    for (int o = 16; o > 0; o >>= 1) v += __shfl_xor_sync(0xffffffffu, v, o);
    int w = threadIdx.x >> 5;
    if ((threadIdx.x & 31) == 0) sred[w] = v;
    __syncthreads();
    float t = sred[threadIdx.x & 7];
#pragma unroll
    for (int o = 4; o > 0; o >>= 1) t += __shfl_xor_sync(0xffffffffu, t, o);
    __syncthreads();
    return t;
}

__device__ __forceinline__ uint32_t s2u(const void* p) {
    return (uint32_t)__cvta_generic_to_shared(p);
}

__device__ __forceinline__ uint32_t packbf(float a, float b) {
    __nv_bfloat162 t = __floats2bfloat162_rn(a, b);
    return *reinterpret_cast<uint32_t*>(&t);
}

#define LDMX4(r, addr)                                                         \
    asm volatile("ldmatrix.sync.aligned.m8n8.x4.shared.b16 {%0,%1,%2,%3}, [%4];" \
        : "=r"((r)[0]), "=r"((r)[1]), "=r"((r)[2]), "=r"((r)[3]) : "r"(addr))

#define LDMX4T(r, addr)                                                        \
    asm volatile("ldmatrix.sync.aligned.m8n8.x4.trans.shared.b16 {%0,%1,%2,%3}, [%4];" \
        : "=r"((r)[0]), "=r"((r)[1]), "=r"((r)[2]), "=r"((r)[3]) : "r"(addr))

#define MMA16816(d, a, b0, b1)                                                 \
    asm volatile("mma.sync.aligned.m16n8k16.row.col.f32.bf16.bf16.f32 "        \
        "{%0,%1,%2,%3}, {%4,%5,%6,%7}, {%8,%9}, {%0,%1,%2,%3};"                \
        : "+f"((d)[0]), "+f"((d)[1]), "+f"((d)[2]), "+f"((d)[3])               \
        : "r"((a)[0]), "r"((a)[1]), "r"((a)[2]), "r"((a)[3]), "r"(b0), "r"(b1))

// ---------------- embedding: h = token_emb[x] + pos_emb ----------------
__global__ __launch_bounds__(256) void embed_kernel(
    const int* __restrict__ x, const float* __restrict__ tok,
    const float* __restrict__ pos, float* __restrict__ h)
{
    int i = blockIdx.x * 256 + threadIdx.x;
    int row = i >> 8;
    int d4  = i & 255;
    int n = row & 1023;
    int t = x[row];
    float4 a = ((const float4*)(tok + (size_t)t * DMODEL))[d4];
    float4 p = ((const float4*)(pos + (size_t)n * DMODEL))[d4];
    a.x += p.x; a.y += p.y; a.z += p.z; a.w += p.w;
    ((float4*)(h + (size_t)row * DMODEL))[d4] = a;
}

// ---------------- layernorm ----------------
__global__ __launch_bounds__(256) void ln_kernel(
    const float* __restrict__ in, float* __restrict__ out,
    const float* __restrict__ gw, const float* __restrict__ bw)
{
    __shared__ float sred[8];
    const int row = blockIdx.x;
    const int tid = threadIdx.x;
    float4 v = ((const float4*)(in + (size_t)row * DMODEL))[tid];
    float s = v.x + v.y + v.z + v.w;
    float tot = block_sum256(s, sred);
    float mean = tot * (1.0f / (float)DMODEL);
    float d0 = v.x - mean, d1 = v.y - mean, d2 = v.z - mean, d3 = v.w - mean;
    float s2 = d0 * d0 + d1 * d1 + d2 * d2 + d3 * d3;
    float tot2 = block_sum256(s2, sred);
    float var = tot2 * (1.0f / (float)DMODEL);
    float rstd = rsqrtf(var + 1e-5f);
    float4 gg = ((const float4*)gw)[tid];
    float4 bb = ((const float4*)bw)[tid];
    float4 o;
    o.x = d0 * rstd * gg.x + bb.x;
    o.y = d1 * rstd * gg.y + bb.y;
    o.z = d2 * rstd * gg.z + bb.z;
    o.w = d3 * rstd * gg.w + bb.w;
    ((float4*)(out + (size_t)row * DMODEL))[tid] = o;
}

// ---------------- l2-normalize q and k heads in-place ----------------
__global__ __launch_bounds__(256) void l2n_kernel(float* __restrict__ qkv)
{
    int wid  = (blockIdx.x * 256 + threadIdx.x) >> 5;
    int lane = threadIdx.x & 31;
    int row   = wid >> 5;
    int rem   = wid & 31;
    int which = rem >> 4;
    int h     = rem & 15;
    float* p = qkv + (size_t)row * (3 * DMODEL) + which * DMODEL + h * DHEAD;
    float2 v = *(float2*)(p + lane * 2);
    float ss = v.x * v.x + v.y * v.y;
#pragma unroll
    for (int o = 16; o > 0; o >>= 1) ss += __shfl_xor_sync(0xffffffffu, ss, o);
    float inv = rsqrtf(ss);
    v.x *= inv; v.y *= inv;
    *(float2*)(p + lane * 2) = v;
}

// ---------------- flash attention (cosine-sim, causal) ----------------
__global__ __launch_bounds__(256) void flash_kernel(
    const float* __restrict__ qkv, float* __restrict__ out)
{
    __shared__ float Qs[64 * 68];
    __shared__ float Kt[64 * 32];
    __shared__ float Vs[32 * 64];
    __shared__ float Ps[64 * 36];
    __shared__ float red[64 * 4];

    const int bh = blockIdx.x;
    const int qb = blockIdx.y;
    const int b = bh >> 4, h = bh & 15;
    const int tid = threadIdx.x;
    const int r = tid >> 2;
    const int g = tid & 3;

    const float* qbase = qkv + (size_t)b * 1024 * (3 * DMODEL) + h * DHEAD;
    const float* kbase = qbase + DMODEL;
    const float* vbase = qbase + 2 * DMODEL;

    for (int t = tid; t < 64 * 16; t += 256) {
        int row = t >> 4;
        int d4  = (t & 15) << 2;
        float4 v = *(const float4*)(qbase + (size_t)(qb * 64 + row) * (3 * DMODEL) + d4);
        *(float4*)(&Qs[row * 68 + d4]) = v;
    }

    float m_run = -1e30f, l_run = 0.f;
    float acc[16];
#pragma unroll
    for (int i = 0; i < 16; i++) acc[i] = 0.f;

    const int iglob = qb * 64 + r;
    const int nkb = 2 * (qb + 1);
    const int c0 = g * 8;
    const int dd0 = g * 16;

    for (int kb = 0; kb < nkb; kb++) {
        __syncthreads();
        for (int t = tid; t < 512; t += 256) {
            int row = t & 31;
            int d4  = (t >> 5) << 2;
            float4 v = *(const float4*)(kbase + (size_t)(kb * 32 + row) * (3 * DMODEL) + d4);
            Kt[(d4 + 0) * 32 + row] = v.x;
            Kt[(d4 + 1) * 32 + row] = v.y;
            Kt[(d4 + 2) * 32 + row] = v.z;
            Kt[(d4 + 3) * 32 + row] = v.w;
        }
        for (int t = tid; t < 512; t += 256) {
            int row = t >> 4;
            int d4  = (t & 15) << 2;
            *(float4*)(&Vs[row * 64 + d4]) =
                *(const float4*)(vbase + (size_t)(kb * 32 + row) * (3 * DMODEL) + d4);
        }
        __syncthreads();

        float s[8];
#pragma unroll
        for (int j = 0; j < 8; j++) s[j] = 0.f;
#pragma unroll 4
        for (int d = 0; d < 64; d++) {
            float qd = Qs[r * 68 + d];
            float4 k0 = *(const float4*)(&Kt[d * 32 + c0]);
            float4 k1 = *(const float4*)(&Kt[d * 32 + c0 + 4]);
            s[0] = fmaf(qd, k0.x, s[0]); s[1] = fmaf(qd, k0.y, s[1]);
            s[2] = fmaf(qd, k0.z, s[2]); s[3] = fmaf(qd, k0.w, s[3]);
            s[4] = fmaf(qd, k1.x, s[4]); s[5] = fmaf(qd, k1.y, s[5]);
            s[6] = fmaf(qd, k1.z, s[6]); s[7] = fmaf(qd, k1.w, s[7]);
        }
        float lmax = -1e30f;
#pragma unroll
        for (int j = 0; j < 8; j++) {
            int jg = kb * 32 + c0 + j;
            s[j] = (jg <= iglob) ? s[j] * 8.0f : -1e30f;
            lmax = fmaxf(lmax, s[j]);
        }
        red[r * 4 + g] = lmax;
        __syncthreads();
        float tmax = fmaxf(fmaxf(red[r * 4 + 0], red[r * 4 + 1]),
                           fmaxf(red[r * 4 + 2], red[r * 4 + 3]));
        float m_new = fmaxf(m_run, tmax);
        float alpha = __expf(m_run - m_new);
        float lsum = 0.f;
#pragma unroll
        for (int j = 0; j < 8; j++) { float p = __expf(s[j] - m_new); s[j] = p; lsum += p; }
        __syncthreads();
        red[r * 4 + g] = lsum;
        *(float4*)(&Ps[r * 36 + c0])     = make_float4(s[0], s[1], s[2], s[3]);
        *(float4*)(&Ps[r * 36 + c0 + 4]) = make_float4(s[4], s[5], s[6], s[7]);
        __syncthreads();
        float tsum = red[r * 4 + 0] + red[r * 4 + 1] + red[r * 4 + 2] + red[r * 4 + 3];
        l_run = l_run * alpha + tsum;
        m_run = m_new;
#pragma unroll
        for (int i = 0; i < 16; i++) acc[i] *= alpha;
        for (int j = 0; j < 32; j++) {
            float p = Ps[r * 36 + j];
            const float4* v4 = (const float4*)(&Vs[j * 64 + dd0]);
            float4 v0 = v4[0], v1 = v4[1], v2 = v4[2], v3 = v4[3];
            acc[0]  = fmaf(p, v0.x, acc[0]);  acc[1]  = fmaf(p, v0.y, acc[1]);
            acc[2]  = fmaf(p, v0.z, acc[2]);  acc[3]  = fmaf(p, v0.w, acc[3]);
            acc[4]  = fmaf(p, v1.x, acc[4]);  acc[5]  = fmaf(p, v1.y, acc[5]);
            acc[6]  = fmaf(p, v1.z, acc[6]);  acc[7]  = fmaf(p, v1.w, acc[7]);
            acc[8]  = fmaf(p, v2.x, acc[8]);  acc[9]  = fmaf(p, v2.y, acc[9]);
            acc[10] = fmaf(p, v2.z, acc[10]); acc[11] = fmaf(p, v2.w, acc[11]);
            acc[12] = fmaf(p, v3.x, acc[12]); acc[13] = fmaf(p, v3.y, acc[13]);
            acc[14] = fmaf(p, v3.z, acc[14]); acc[15] = fmaf(p, v3.w, acc[15]);
        }
    }
    float inv = 1.f / l_run;
    float* ob = out + (size_t)(b * 1024 + iglob) * DMODEL + h * DHEAD + dd0;
#pragma unroll
    for (int q = 0; q < 4; q++) {
        float4 v = make_float4(acc[q * 4] * inv, acc[q * 4 + 1] * inv,
                               acc[q * 4 + 2] * inv, acc[q * 4 + 3] * inv);
        *(float4*)(ob + q * 4) = v;
    }
}

// ---------------- 3xBF16 mma.sync GEMM: 128x128x32 tiles ----------------
// C = A @ B with fp32 data; A[m][k], B[k][n] row-major.
// Split each operand x = hi + lo (bf16), compute hi*hi + hi*lo + lo*hi.
// EPI: 0=none, 1=+bias, 2=+bias+gelu, 3=+residual, 4=+bias+residual
template<int EPI>
__global__ __launch_bounds__(256, 2) void hgemm_kernel(
    const float* __restrict__ A, const float* __restrict__ Bw, float* __restrict__ C,
    int K, int N, const float* __restrict__ bias, const float* __restrict__ res)
{
    __shared__ __align__(16) __nv_bfloat16 Ah[128][40];   // [m][k], pad 40
    __shared__ __align__(16) __nv_bfloat16 Al[128][40];
    __shared__ __align__(16) __nv_bfloat16 Bh[32][136];   // [k][n], pad 136
    __shared__ __align__(16) __nv_bfloat16 Bl[32][136];

    const int tid  = threadIdx.x;
    const int bn   = blockIdx.x, bm = blockIdx.y;
    const int lane = tid & 31, warp = tid >> 5;
    const int wm   = warp & 3;   // m strip of 32
    const int wn   = warp >> 2;  // n strip of 64

    float acc[2][8][4];
#pragma unroll
    for (int i = 0; i < 2; i++)
#pragma unroll
        for (int j = 0; j < 8; j++)
#pragma unroll
            for (int q = 0; q < 4; q++) acc[i][j][q] = 0.f;

    // global load assignments
    const int am  = tid >> 1;            // A row 0..127
    const int akh = (tid & 1) * 16;      // A k-half
    const float* Aptr = A + (size_t)(bm * 128 + am) * K + akh;
    const int bk0 = tid >> 5;            // B k-row 0..7 (stride 8)
    const int bc4 = (tid & 31) * 4;      // B n offset
    const float* Bptr = Bw + (size_t)bk0 * N + (size_t)bn * 128 + bc4;

    // ldmatrix base addresses
    uint32_t aH[2], aL[2], bHa[4], bLa[4];
    {
        int r = wm * 32 + (lane & 7) + ((lane >> 3) & 1) * 8;
        int c = (lane >> 4) * 8;
        aH[0] = s2u(&Ah[r][c]);      aH[1] = s2u(&Ah[r + 16][c]);
        aL[0] = s2u(&Al[r][c]);      aL[1] = s2u(&Al[r + 16][c]);
        int br = (lane & 7) + ((lane >> 3) & 1) * 8;
        int bc = wn * 64 + (lane >> 4) * 8;
#pragma unroll
        for (int p = 0; p < 4; p++) {
            bHa[p] = s2u(&Bh[br][bc + p * 16]);
            bLa[p] = s2u(&Bl[br][bc + p * 16]);
        }
    }

    for (int kt = 0; kt < K; kt += 32) {
        __syncthreads();
        // ---- A tile: 128x32, convert to hi/lo bf16 ----
        {
            float4 u0 = *(const float4*)(Aptr + kt);
            float4 u1 = *(const float4*)(Aptr + kt + 4);
            float4 u2 = *(const float4*)(Aptr + kt + 8);
            float4 u3 = *(const float4*)(Aptr + kt + 12);
            float v[16] = {u0.x,u0.y,u0.z,u0.w, u1.x,u1.y,u1.z,u1.w,
                           u2.x,u2.y,u2.z,u2.w, u3.x,u3.y,u3.z,u3.w};
            uint32_t hp[8], lp[8];
#pragma unroll
            for (int j = 0; j < 8; j++) {
                float x0 = v[2*j], x1 = v[2*j+1];
                float h0 = __bfloat162float(__float2bfloat16_rn(x0));
                float h1 = __bfloat162float(__float2bfloat16_rn(x1));
                hp[j] = packbf(h0, h1);
                lp[j] = packbf(x0 - h0, x1 - h1);
            }
            *(uint4*)&Ah[am][akh]     = make_uint4(hp[0], hp[1], hp[2], hp[3]);
            *(uint4*)&Ah[am][akh + 8] = make_uint4(hp[4], hp[5], hp[6], hp[7]);
            *(uint4*)&Al[am][akh]     = make_uint4(lp[0], lp[1], lp[2], lp[3]);
            *(uint4*)&Al[am][akh + 8] = make_uint4(lp[4], lp[5], lp[6], lp[7]);
        }
        // ---- B tile: 32x128, convert to hi/lo bf16 (keep [k][n]) ----
#pragma unroll
        for (int i = 0; i < 4; i++) {
            float4 v = *(const float4*)(Bptr + (size_t)(kt + i * 8) * N);
            float h0 = __bfloat162float(__float2bfloat16_rn(v.x));
            float h1 = __bfloat162float(__float2bfloat16_rn(v.y));
            float h2 = __bfloat162float(__float2bfloat16_rn(v.z));
            float h3 = __bfloat162float(__float2bfloat16_rn(v.w));
            int kr = bk0 + i * 8;
            *(uint2*)&Bh[kr][bc4] = make_uint2(packbf(h0, h1), packbf(h2, h3));
            *(uint2*)&Bl[kr][bc4] = make_uint2(packbf(v.x - h0, v.y - h1),
                                               packbf(v.z - h2, v.w - h3));
        }
        __syncthreads();

        // ---- MMA phase: 2 k-steps of 16 ----
#pragma unroll
        for (int ks = 0; ks < 2; ks++) {
            const uint32_t ao = ks * 32;     // 16 bf16 cols
            const uint32_t bo = ks * 4352;   // 16 rows * 272B
            uint32_t a_h[2][4], a_l[2][4], bfr[4][4];
            LDMX4(a_h[0], aH[0] + ao);
            LDMX4(a_h[1], aH[1] + ao);
            LDMX4(a_l[0], aL[0] + ao);
            LDMX4(a_l[1], aL[1] + ao);
#pragma unroll
            for (int p = 0; p < 4; p++) LDMX4T(bfr[p], bHa[p] + bo);
            // hi*hi and lo*hi
#pragma unroll
            for (int mt = 0; mt < 2; mt++)
#pragma unroll
                for (int nt = 0; nt < 8; nt++) {
                    uint32_t b0 = bfr[nt >> 1][(nt & 1) * 2];
                    uint32_t b1 = bfr[nt >> 1][(nt & 1) * 2 + 1];
                    MMA16816(acc[mt][nt], a_h[mt], b0, b1);
                    MMA16816(acc[mt][nt], a_l[mt], b0, b1);
                }
            // hi*lo
#pragma unroll
            for (int p = 0; p < 4; p++) LDMX4T(bfr[p], bLa[p] + bo);
#pragma unroll
            for (int mt = 0; mt < 2; mt++)
#pragma unroll
                for (int nt = 0; nt < 8; nt++) {
                    uint32_t b0 = bfr[nt >> 1][(nt & 1) * 2];
                    uint32_t b1 = bfr[nt >> 1][(nt & 1) * 2 + 1];
                    MMA16816(acc[mt][nt], a_h[mt], b0, b1);
                }
        }
    }

    // ---- epilogue ----
    const int g  = lane >> 2;
    const int tg = lane & 3;
#pragma unroll
    for (int mt = 0; mt < 2; mt++) {
        int row = bm * 128 + wm * 32 + mt * 16 + g;
#pragma unroll
        for (int nt = 0; nt < 8; nt++) {
            int col = bn * 128 + wn * 64 + nt * 8 + tg * 2;
            float d0 = acc[mt][nt][0], d1 = acc[mt][nt][1];
            float d2 = acc[mt][nt][2], d3 = acc[mt][nt][3];
            if (EPI == 1 || EPI == 2 || EPI == 4) {
                float2 bb = *(const float2*)(bias + col);
                d0 += bb.x; d1 += bb.y; d2 += bb.x; d3 += bb.y;
            }
            if (EPI == 2) {
                d0 = geluf(d0); d1 = geluf(d1); d2 = geluf(d2); d3 = geluf(d3);
            }
            size_t off0 = (size_t)row * N + col;
            size_t off1 = (size_t)(row + 8) * N + col;
            if (EPI == 3 || EPI == 4) {
                float2 r0 = *(const float2*)(res + off0);
                float2 r1 = *(const float2*)(res + off1);
                d0 += r0.x; d1 += r0.y; d2 += r1.x; d3 += r1.y;
            }
            *(float2*)(C + off0) = make_float2(d0, d1);
            *(float2*)(C + off1) = make_float2(d2, d3);
        }
    }
}

// ---------------- launch ----------------
extern "C" void kernel_launch(void* const* d_in, const int* in_sizes, int n_in,
                              void* d_out, int out_size)
{
    const int*   x       = (const int*)  d_in[0];
    const float* tok     = (const float*)d_in[1];
    const float* pos     = (const float*)d_in[2];
    const float* ln1_g   = (const float*)d_in[3];
    const float* ln1_b   = (const float*)d_in[4];
    const float* w_qkv   = (const float*)d_in[5];
    const float* w_out   = (const float*)d_in[6];
    const float* ln2_g   = (const float*)d_in[7];
    const float* ln2_b   = (const float*)d_in[8];
    const float* w1      = (const float*)d_in[9];
    const float* b1      = (const float*)d_in[10];
    const float* w2      = (const float*)d_in[11];
    const float* b2      = (const float*)d_in[12];
    const float* lnf_g   = (const float*)d_in[13];
    const float* lnf_b   = (const float*)d_in[14];
    const float* w_logit = (const float*)d_in[15];
    const float* b_logit = (const float*)d_in[16];
    float* out = (float*)d_out;

    void *ph, *pxn, *pqkv, *po, *pff;
    cudaGetSymbolAddress(&ph,  g_h);
    cudaGetSymbolAddress(&pxn, g_xn);
    cudaGetSymbolAddress(&pqkv,g_qkv);
    cudaGetSymbolAddress(&po,  g_o);
    cudaGetSymbolAddress(&pff, g_ff);
    float* h   = (float*)ph;
    float* xn  = (float*)pxn;
    float* qkv = (float*)pqkv;
    float* o   = (float*)po;
    float* ff  = (float*)pff;

    embed_kernel<<<2048, 256>>>(x, tok, pos, h);

    for (int l = 0; l < NLAYER; l++) {
        ln_kernel<<<NROWS, 256>>>(h, xn, ln1_g + l * DMODEL, ln1_b + l * DMODEL);
        hgemm_kernel<0><<<dim3(3072 / 128, NROWS / 128), 256>>>(
            xn, w_qkv + (size_t)l * DMODEL * 3072, qkv, DMODEL, 3072, nullptr, nullptr);
        l2n_kernel<<<8192, 256>>>(qkv);
        flash_kernel<<<dim3(32, 16), 256>>>(qkv, o);
        hgemm_kernel<3><<<dim3(DMODEL / 128, NROWS / 128), 256>>>(
            o, w_out + (size_t)l * DMODEL * DMODEL, h, DMODEL, DMODEL, nullptr, h);
        ln_kernel<<<NROWS, 256>>>(h, xn, ln2_g + l * DMODEL, ln2_b + l * DMODEL);
        hgemm_kernel<2><<<dim3(DFF / 128, NROWS / 128), 256>>>(
            xn, w1 + (size_t)l * DMODEL * DFF, ff, DMODEL, DFF, b1 + l * DFF, nullptr);
        hgemm_kernel<4><<<dim3(DMODEL / 128, NROWS / 128), 256>>>(
            ff, w2 + (size_t)l * DFF * DMODEL, h, DFF, DMODEL, b2 + l * DMODEL, h);
    }

    ln_kernel<<<NROWS, 256>>>(h, xn, lnf_g, lnf_b);
    hgemm_kernel<1><<<dim3(NVOCAB / 128, NROWS / 128), 256>>>(
        xn, w_logit, out, DMODEL, NVOCAB, b_logit, nullptr);
}

// round 4
// speedup vs baseline: 1.9359x; 1.0015x over previous
#include <cuda_runtime.h>
#include <cuda_bf16.h>
#include <math.h>
#include <stdint.h>

// Problem constants
#define NROWS  2048      // B*N
#define DMODEL 1024
#define NHEAD  16
#define DHEAD  64
#define DFF    4096
#define NVOCAB 32000
#define NLAYER 6

// ---------------- device scratch (no allocation allowed) ----------------
__device__ float g_h  [NROWS * DMODEL];
__device__ float g_xn [NROWS * DMODEL];
__device__ float g_qkv[NROWS * 3 * DMODEL];
__device__ float g_o  [NROWS * DMODEL];
__device__ float g_ff [NROWS * DFF];

// ---------------- helpers ----------------
__device__ __forceinline__ float geluf(float x) {
    return 0.5f * x * (1.0f + erff(x * 0.70710678118654752f));
}

__device__ __forceinline__ float block_sum256(float v, float* sred) {
#pragma unroll
    for (int o = 16; o > 0; o >>= 1) v += __shfl_xor_sync(0xffffffffu, v, o);
    int w = threadIdx.x >> 5;
    if ((threadIdx.x & 31) == 0) sred[w] = v;
    __syncthreads();
    float t = sred[threadIdx.x & 7];
#pragma unroll
    for (int o = 4; o > 0; o >>= 1) t += __shfl_xor_sync(0xffffffffu, t, o);
    __syncthreads();
    return t;
}

__device__ __forceinline__ uint32_t s2u(const void* p) {
    return (uint32_t)__cvta_generic_to_shared(p);
}

__device__ __forceinline__ uint32_t packbf(float a, float b) {
    __nv_bfloat162 t = __floats2bfloat162_rn(a, b);
    return *reinterpret_cast<uint32_t*>(&t);
}

#define LDMX4(r, addr)                                                         \
    asm volatile("ldmatrix.sync.aligned.m8n8.x4.shared.b16 {%0,%1,%2,%3}, [%4];" \
        : "=r"((r)[0]), "=r"((r)[1]), "=r"((r)[2]), "=r"((r)[3]) : "r"(addr))

#define LDMX4T(r, addr)                                                        \
    asm volatile("ldmatrix.sync.aligned.m8n8.x4.trans.shared.b16 {%0,%1,%2,%3}, [%4];" \
        : "=r"((r)[0]), "=r"((r)[1]), "=r"((r)[2]), "=r"((r)[3]) : "r"(addr))

#define MMA16816(d, a, b0, b1)                                                 \
    asm volatile("mma.sync.aligned.m16n8k16.row.col.f32.bf16.bf16.f32 "        \
        "{%0,%1,%2,%3}, {%4,%5,%6,%7}, {%8,%9}, {%0,%1,%2,%3};"                \
        : "+f"((d)[0]), "+f"((d)[1]), "+f"((d)[2]), "+f"((d)[3])               \
        : "r"((a)[0]), "r"((a)[1]), "r"((a)[2]), "r"((a)[3]), "r"(b0), "r"(b1))

// ---------------- embedding: h = token_emb[x] + pos_emb ----------------
__global__ __launch_bounds__(256) void embed_kernel(
    const int* __restrict__ x, const float* __restrict__ tok,
    const float* __restrict__ pos, float* __restrict__ h)
{
    int i = blockIdx.x * 256 + threadIdx.x;
    int row = i >> 8;
    int d4  = i & 255;
    int n = row & 1023;
    int t = x[row];
    float4 a = ((const float4*)(tok + (size_t)t * DMODEL))[d4];
    float4 p = ((const float4*)(pos + (size_t)n * DMODEL))[d4];
    a.x += p.x; a.y += p.y; a.z += p.z; a.w += p.w;
    ((float4*)(h + (size_t)row * DMODEL))[d4] = a;
}

// ---------------- layernorm ----------------
__global__ __launch_bounds__(256) void ln_kernel(
    const float* __restrict__ in, float* __restrict__ out,
    const float* __restrict__ gw, const float* __restrict__ bw)
{
    __shared__ float sred[8];
    const int row = blockIdx.x;
    const int tid = threadIdx.x;
    float4 v = ((const float4*)(in + (size_t)row * DMODEL))[tid];
    float s = v.x + v.y + v.z + v.w;
    float tot = block_sum256(s, sred);
    float mean = tot * (1.0f / (float)DMODEL);
    float d0 = v.x - mean, d1 = v.y - mean, d2 = v.z - mean, d3 = v.w - mean;
    float s2 = d0 * d0 + d1 * d1 + d2 * d2 + d3 * d3;
    float tot2 = block_sum256(s2, sred);
    float var = tot2 * (1.0f / (float)DMODEL);
    float rstd = rsqrtf(var + 1e-5f);
    float4 gg = ((const float4*)gw)[tid];
    float4 bb = ((const float4*)bw)[tid];
    float4 o;
    o.x = d0 * rstd * gg.x + bb.x;
    o.y = d1 * rstd * gg.y + bb.y;
    o.z = d2 * rstd * gg.z + bb.z;
    o.w = d3 * rstd * gg.w + bb.w;
    ((float4*)(out + (size_t)row * DMODEL))[tid] = o;
}

// ---------------- l2-normalize q and k heads in-place ----------------
__global__ __launch_bounds__(256) void l2n_kernel(float* __restrict__ qkv)
{
    int wid  = (blockIdx.x * 256 + threadIdx.x) >> 5;
    int lane = threadIdx.x & 31;
    int row   = wid >> 5;
    int rem   = wid & 31;
    int which = rem >> 4;
    int h     = rem & 15;
    float* p = qkv + (size_t)row * (3 * DMODEL) + which * DMODEL + h * DHEAD;
    float2 v = *(float2*)(p + lane * 2);
    float ss = v.x * v.x + v.y * v.y;
#pragma unroll
    for (int o = 16; o > 0; o >>= 1) ss += __shfl_xor_sync(0xffffffffu, ss, o);
    float inv = rsqrtf(ss);
    v.x *= inv; v.y *= inv;
    *(float2*)(p + lane * 2) = v;
}

// ---------------- flash attention (cosine-sim, causal) ----------------
__global__ __launch_bounds__(256) void flash_kernel(
    const float* __restrict__ qkv, float* __restrict__ out)
{
    __shared__ float Qs[64 * 68];
    __shared__ float Kt[64 * 32];
    __shared__ float Vs[32 * 64];
    __shared__ float Ps[64 * 36];
    __shared__ float red[64 * 4];

    const int bh = blockIdx.x;
    const int qb = blockIdx.y;
    const int b = bh >> 4, h = bh & 15;
    const int tid = threadIdx.x;
    const int r = tid >> 2;
    const int g = tid & 3;

    const float* qbase = qkv + (size_t)b * 1024 * (3 * DMODEL) + h * DHEAD;
    const float* kbase = qbase + DMODEL;
    const float* vbase = qbase + 2 * DMODEL;

    for (int t = tid; t < 64 * 16; t += 256) {
        int row = t >> 4;
        int d4  = (t & 15) << 2;
        float4 v = *(const float4*)(qbase + (size_t)(qb * 64 + row) * (3 * DMODEL) + d4);
        *(float4*)(&Qs[row * 68 + d4]) = v;
    }

    float m_run = -1e30f, l_run = 0.f;
    float acc[16];
#pragma unroll
    for (int i = 0; i < 16; i++) acc[i] = 0.f;

    const int iglob = qb * 64 + r;
    const int nkb = 2 * (qb + 1);
    const int c0 = g * 8;
    const int dd0 = g * 16;

    for (int kb = 0; kb < nkb; kb++) {
        __syncthreads();
        for (int t = tid; t < 512; t += 256) {
            int row = t & 31;
            int d4  = (t >> 5) << 2;
            float4 v = *(const float4*)(kbase + (size_t)(kb * 32 + row) * (3 * DMODEL) + d4);
            Kt[(d4 + 0) * 32 + row] = v.x;
            Kt[(d4 + 1) * 32 + row] = v.y;
            Kt[(d4 + 2) * 32 + row] = v.z;
            Kt[(d4 + 3) * 32 + row] = v.w;
        }
        for (int t = tid; t < 512; t += 256) {
            int row = t >> 4;
            int d4  = (t & 15) << 2;
            *(float4*)(&Vs[row * 64 + d4]) =
                *(const float4*)(vbase + (size_t)(kb * 32 + row) * (3 * DMODEL) + d4);
        }
        __syncthreads();

        float s[8];
#pragma unroll
        for (int j = 0; j < 8; j++) s[j] = 0.f;
#pragma unroll 4
        for (int d = 0; d < 64; d++) {
            float qd = Qs[r * 68 + d];
            float4 k0 = *(const float4*)(&Kt[d * 32 + c0]);
            float4 k1 = *(const float4*)(&Kt[d * 32 + c0 + 4]);
            s[0] = fmaf(qd, k0.x, s[0]); s[1] = fmaf(qd, k0.y, s[1]);
            s[2] = fmaf(qd, k0.z, s[2]); s[3] = fmaf(qd, k0.w, s[3]);
            s[4] = fmaf(qd, k1.x, s[4]); s[5] = fmaf(qd, k1.y, s[5]);
            s[6] = fmaf(qd, k1.z, s[6]); s[7] = fmaf(qd, k1.w, s[7]);
        }
        float lmax = -1e30f;
#pragma unroll
        for (int j = 0; j < 8; j++) {
            int jg = kb * 32 + c0 + j;
            s[j] = (jg <= iglob) ? s[j] * 8.0f : -1e30f;
            lmax = fmaxf(lmax, s[j]);
        }
        red[r * 4 + g] = lmax;
        __syncthreads();
        float tmax = fmaxf(fmaxf(red[r * 4 + 0], red[r * 4 + 1]),
                           fmaxf(red[r * 4 + 2], red[r * 4 + 3]));
        float m_new = fmaxf(m_run, tmax);
        float alpha = __expf(m_run - m_new);
        float lsum = 0.f;
#pragma unroll
        for (int j = 0; j < 8; j++) { float p = __expf(s[j] - m_new); s[j] = p; lsum += p; }
        __syncthreads();
        red[r * 4 + g] = lsum;
        *(float4*)(&Ps[r * 36 + c0])     = make_float4(s[0], s[1], s[2], s[3]);
        *(float4*)(&Ps[r * 36 + c0 + 4]) = make_float4(s[4], s[5], s[6], s[7]);
        __syncthreads();
        float tsum = red[r * 4 + 0] + red[r * 4 + 1] + red[r * 4 + 2] + red[r * 4 + 3];
        l_run = l_run * alpha + tsum;
        m_run = m_new;
#pragma unroll
        for (int i = 0; i < 16; i++) acc[i] *= alpha;
        for (int j = 0; j < 32; j++) {
            float p = Ps[r * 36 + j];
            const float4* v4 = (const float4*)(&Vs[j * 64 + dd0]);
            float4 v0 = v4[0], v1 = v4[1], v2 = v4[2], v3 = v4[3];
            acc[0]  = fmaf(p, v0.x, acc[0]);  acc[1]  = fmaf(p, v0.y, acc[1]);
            acc[2]  = fmaf(p, v0.z, acc[2]);  acc[3]  = fmaf(p, v0.w, acc[3]);
            acc[4]  = fmaf(p, v1.x, acc[4]);  acc[5]  = fmaf(p, v1.y, acc[5]);
            acc[6]  = fmaf(p, v1.z, acc[6]);  acc[7]  = fmaf(p, v1.w, acc[7]);
            acc[8]  = fmaf(p, v2.x, acc[8]);  acc[9]  = fmaf(p, v2.y, acc[9]);
            acc[10] = fmaf(p, v2.z, acc[10]); acc[11] = fmaf(p, v2.w, acc[11]);
            acc[12] = fmaf(p, v3.x, acc[12]); acc[13] = fmaf(p, v3.y, acc[13]);
            acc[14] = fmaf(p, v3.z, acc[14]); acc[15] = fmaf(p, v3.w, acc[15]);
        }
    }
    float inv = 1.f / l_run;
    float* ob = out + (size_t)(b * 1024 + iglob) * DMODEL + h * DHEAD + dd0;
#pragma unroll
    for (int q = 0; q < 4; q++) {
        float4 v = make_float4(acc[q * 4] * inv, acc[q * 4 + 1] * inv,
                               acc[q * 4 + 2] * inv, acc[q * 4 + 3] * inv);
        *(float4*)(ob + q * 4) = v;
    }
}

// ---------------- 3xBF16 mma.sync GEMM: 128x128x32 tiles ----------------
// C = A @ B with fp32 data; A[m][k], B[k][n] row-major.
// Split each operand x = hi + lo (bf16), compute hi*hi + hi*lo + lo*hi.
// EPI: 0=none, 1=+bias, 2=+bias+gelu, 3=+residual, 4=+bias+residual
template<int EPI>
__global__ __launch_bounds__(256, 2) void hgemm_kernel(
    const float* __restrict__ A, const float* __restrict__ Bw, float* __restrict__ C,
    int K, int N, const float* __restrict__ bias, const float* __restrict__ res)
{
    __shared__ __align__(16) __nv_bfloat16 Ah[128][40];   // [m][k], pad 40
    __shared__ __align__(16) __nv_bfloat16 Al[128][40];
    __shared__ __align__(16) __nv_bfloat16 Bh[32][136];   // [k][n], pad 136
    __shared__ __align__(16) __nv_bfloat16 Bl[32][136];

    const int tid  = threadIdx.x;
    const int bn   = blockIdx.x, bm = blockIdx.y;
    const int lane = tid & 31, warp = tid >> 5;
    const int wm   = warp & 3;   // m strip of 32
    const int wn   = warp >> 2;  // n strip of 64

    float acc[2][8][4];
#pragma unroll
    for (int i = 0; i < 2; i++)
#pragma unroll
        for (int j = 0; j < 8; j++)
#pragma unroll
            for (int q = 0; q < 4; q++) acc[i][j][q] = 0.f;

    // global load assignments
    const int am  = tid >> 1;            // A row 0..127
    const int akh = (tid & 1) * 16;      // A k-half
    const float* Aptr = A + (size_t)(bm * 128 + am) * K + akh;
    const int bk0 = tid >> 5;            // B k-row 0..7 (stride 8)
    const int bc4 = (tid & 31) * 4;      // B n offset
    const float* Bptr = Bw + (size_t)bk0 * N + (size_t)bn * 128 + bc4;

    // ldmatrix base addresses
    uint32_t aH[2], aL[2], bHa[4], bLa[4];
    {
        int r = wm * 32 + (lane & 7) + ((lane >> 3) & 1) * 8;
        int c = (lane >> 4) * 8;
        aH[0] = s2u(&Ah[r][c]);      aH[1] = s2u(&Ah[r + 16][c]);
        aL[0] = s2u(&Al[r][c]);      aL[1] = s2u(&Al[r + 16][c]);
        int br = (lane & 7) + ((lane >> 3) & 1) * 8;
        int bc = wn * 64 + (lane >> 4) * 8;
#pragma unroll
        for (int p = 0; p < 4; p++) {
            bHa[p] = s2u(&Bh[br][bc + p * 16]);
            bLa[p] = s2u(&Bl[br][bc + p * 16]);
        }
    }

    for (int kt = 0; kt < K; kt += 32) {
        __syncthreads();
        // ---- A tile: 128x32, convert to hi/lo bf16 ----
        {
            float4 u0 = *(const float4*)(Aptr + kt);
            float4 u1 = *(const float4*)(Aptr + kt + 4);
            float4 u2 = *(const float4*)(Aptr + kt + 8);
            float4 u3 = *(const float4*)(Aptr + kt + 12);
            float v[16] = {u0.x,u0.y,u0.z,u0.w, u1.x,u1.y,u1.z,u1.w,
                           u2.x,u2.y,u2.z,u2.w, u3.x,u3.y,u3.z,u3.w};
            uint32_t hp[8], lp[8];
#pragma unroll
            for (int j = 0; j < 8; j++) {
                float x0 = v[2*j], x1 = v[2*j+1];
                float h0 = __bfloat162float(__float2bfloat16_rn(x0));
                float h1 = __bfloat162float(__float2bfloat16_rn(x1));
                hp[j] = packbf(h0, h1);
                lp[j] = packbf(x0 - h0, x1 - h1);
            }
            *(uint4*)&Ah[am][akh]     = make_uint4(hp[0], hp[1], hp[2], hp[3]);
            *(uint4*)&Ah[am][akh + 8] = make_uint4(hp[4], hp[5], hp[6], hp[7]);
            *(uint4*)&Al[am][akh]     = make_uint4(lp[0], lp[1], lp[2], lp[3]);
            *(uint4*)&Al[am][akh + 8] = make_uint4(lp[4], lp[5], lp[6], lp[7]);
        }
        // ---- B tile: 32x128, convert to hi/lo bf16 (keep [k][n]) ----
#pragma unroll
        for (int i = 0; i < 4; i++) {
            float4 v = *(const float4*)(Bptr + (size_t)(kt + i * 8) * N);
            float h0 = __bfloat162float(__float2bfloat16_rn(v.x));
            float h1 = __bfloat162float(__float2bfloat16_rn(v.y));
            float h2 = __bfloat162float(__float2bfloat16_rn(v.z));
            float h3 = __bfloat162float(__float2bfloat16_rn(v.w));
            int kr = bk0 + i * 8;
            *(uint2*)&Bh[kr][bc4] = make_uint2(packbf(h0, h1), packbf(h2, h3));
            *(uint2*)&Bl[kr][bc4] = make_uint2(packbf(v.x - h0, v.y - h1),
                                               packbf(v.z - h2, v.w - h3));
        }
        __syncthreads();

        // ---- MMA phase: 2 k-steps of 16 ----
#pragma unroll
        for (int ks = 0; ks < 2; ks++) {
            const uint32_t ao = ks * 32;     // 16 bf16 cols
            const uint32_t bo = ks * 4352;   // 16 rows * 272B
            uint32_t a_h[2][4], a_l[2][4], bfr[4][4];
            LDMX4(a_h[0], aH[0] + ao);
            LDMX4(a_h[1], aH[1] + ao);
            LDMX4(a_l[0], aL[0] + ao);
            LDMX4(a_l[1], aL[1] + ao);
#pragma unroll
            for (int p = 0; p < 4; p++) LDMX4T(bfr[p], bHa[p] + bo);
            // hi*hi and lo*hi
#pragma unroll
            for (int mt = 0; mt < 2; mt++)
#pragma unroll
                for (int nt = 0; nt < 8; nt++) {
                    uint32_t b0 = bfr[nt >> 1][(nt & 1) * 2];
                    uint32_t b1 = bfr[nt >> 1][(nt & 1) * 2 + 1];
                    MMA16816(acc[mt][nt], a_h[mt], b0, b1);
                    MMA16816(acc[mt][nt], a_l[mt], b0, b1);
                }
            // hi*lo
#pragma unroll
            for (int p = 0; p < 4; p++) LDMX4T(bfr[p], bLa[p] + bo);
#pragma unroll
            for (int mt = 0; mt < 2; mt++)
#pragma unroll
                for (int nt = 0; nt < 8; nt++) {
                    uint32_t b0 = bfr[nt >> 1][(nt & 1) * 2];
                    uint32_t b1 = bfr[nt >> 1][(nt & 1) * 2 + 1];
                    MMA16816(acc[mt][nt], a_h[mt], b0, b1);
                }
        }
    }

    // ---- epilogue ----
    const int g  = lane >> 2;
    const int tg = lane & 3;
#pragma unroll
    for (int mt = 0; mt < 2; mt++) {
        int row = bm * 128 + wm * 32 + mt * 16 + g;
#pragma unroll
        for (int nt = 0; nt < 8; nt++) {
            int col = bn * 128 + wn * 64 + nt * 8 + tg * 2;
            float d0 = acc[mt][nt][0], d1 = acc[mt][nt][1];
            float d2 = acc[mt][nt][2], d3 = acc[mt][nt][3];
            if (EPI == 1 || EPI == 2 || EPI == 4) {
                float2 bb = *(const float2*)(bias + col);
                d0 += bb.x; d1 += bb.y; d2 += bb.x; d3 += bb.y;
            }
            if (EPI == 2) {
                d0 = geluf(d0); d1 = geluf(d1); d2 = geluf(d2); d3 = geluf(d3);
            }
            size_t off0 = (size_t)row * N + col;
            size_t off1 = (size_t)(row + 8) * N + col;
            if (EPI == 3 || EPI == 4) {
                float2 r0 = *(const float2*)(res + off0);
                float2 r1 = *(const float2*)(res + off1);
                d0 += r0.x; d1 += r0.y; d2 += r1.x; d3 += r1.y;
            }
            *(float2*)(C + off0) = make_float2(d0, d1);
            *(float2*)(C + off1) = make_float2(d2, d3);
        }
    }
}

// ---------------- launch ----------------
extern "C" void kernel_launch(void* const* d_in, const int* in_sizes, int n_in,
                              void* d_out, int out_size)
{
    const int*   x       = (const int*)  d_in[0];
    const float* tok     = (const float*)d_in[1];
    const float* pos     = (const float*)d_in[2];
    const float* ln1_g   = (const float*)d_in[3];
    const float* ln1_b   = (const float*)d_in[4];
    const float* w_qkv   = (const float*)d_in[5];
    const float* w_out   = (const float*)d_in[6];
    const float* ln2_g   = (const float*)d_in[7];
    const float* ln2_b   = (const float*)d_in[8];
    const float* w1      = (const float*)d_in[9];
    const float* b1      = (const float*)d_in[10];
    const float* w2      = (const float*)d_in[11];
    const float* b2      = (const float*)d_in[12];
    const float* lnf_g   = (const float*)d_in[13];
    const float* lnf_b   = (const float*)d_in[14];
    const float* w_logit = (const float*)d_in[15];
    const float* b_logit = (const float*)d_in[16];
    float* out = (float*)d_out;

    void *ph, *pxn, *pqkv, *po, *pff;
    cudaGetSymbolAddress(&ph,  g_h);
    cudaGetSymbolAddress(&pxn, g_xn);
    cudaGetSymbolAddress(&pqkv,g_qkv);
    cudaGetSymbolAddress(&po,  g_o);
    cudaGetSymbolAddress(&pff, g_ff);
    float* h   = (float*)ph;
    float* xn  = (float*)pxn;
    float* qkv = (float*)pqkv;
    float* o   = (float*)po;
    float* ff  = (float*)pff;

    embed_kernel<<<2048, 256>>>(x, tok, pos, h);

    for (int l = 0; l < NLAYER; l++) {
        ln_kernel<<<NROWS, 256>>>(h, xn, ln1_g + l * DMODEL, ln1_b + l * DMODEL);
        hgemm_kernel<0><<<dim3(3072 / 128, NROWS / 128), 256>>>(
            xn, w_qkv + (size_t)l * DMODEL * 3072, qkv, DMODEL, 3072, nullptr, nullptr);
        l2n_kernel<<<8192, 256>>>(qkv);
        flash_kernel<<<dim3(32, 16), 256>>>(qkv, o);
        hgemm_kernel<3><<<dim3(DMODEL / 128, NROWS / 128), 256>>>(
            o, w_out + (size_t)l * DMODEL * DMODEL, h, DMODEL, DMODEL, nullptr, h);
        ln_kernel<<<NROWS, 256>>>(h, xn, ln2_g + l * DMODEL, ln2_b + l * DMODEL);
        hgemm_kernel<2><<<dim3(DFF / 128, NROWS / 128), 256>>>(
            xn, w1 + (size_t)l * DMODEL * DFF, ff, DMODEL, DFF, b1 + l * DFF, nullptr);
        hgemm_kernel<4><<<dim3(DMODEL / 128, NROWS / 128), 256>>>(
            ff, w2 + (size_t)l * DFF * DMODEL, h, DFF, DMODEL, b2 + l * DMODEL, h);
    }

    ln_kernel<<<NROWS, 256>>>(h, xn, lnf_g, lnf_b);
    hgemm_kernel<1><<<dim3(NVOCAB / 128, NROWS / 128), 256>>>(
        xn, w_logit, out, DMODEL, NVOCAB, b_logit, nullptr);
}